// round 6
// baseline (speedup 1.0000x reference)
#include <cuda_runtime.h>

// ---------------------------------------------------------------------------
// SparseNetwork2: layered sparse MLP 4096 -> 2048 -> 1024 -> 512 -> 2
// FAN_IN = 128 edges per target node, edges contiguous per target
// (edge_tgt = repeat(arange(s,e), 128)), so the reference's full-edge
// segment_sum collapses to a per-layer gather.
// Per hidden layer: gather + bias, LayerNorm over the layer's nodes per
// batch column (biased var, eps=1e-5), ReLU.
// Activations kept node-major [node][B] in L2-resident device scratch.
// ---------------------------------------------------------------------------

#define BATCH       512
#define INPUT_DIM   4096
#define TOTAL_NODES 7682
#define FAN_IN      128
#define LN_EPS      1e-5f

// 15.7 MB activation scratch (fits in 126 MB L2)
__device__ float g_acts[(size_t)TOTAL_NODES * BATCH];
__device__ float g_mean[BATCH];
__device__ float g_rstd[BATCH];

// ---- transpose x [B, INPUT_DIM] -> g_acts[n*B + b] ------------------------
__global__ void transpose_kernel(const float* __restrict__ x) {
    __shared__ float tile[32][33];
    const int n0 = blockIdx.x * 32;
    const int b0 = blockIdx.y * 32;
    const int tx = threadIdx.x, ty = threadIdx.y;
    #pragma unroll
    for (int i = ty; i < 32; i += 8)
        tile[i][tx] = x[(size_t)(b0 + i) * INPUT_DIM + (n0 + tx)];
    __syncthreads();
    #pragma unroll
    for (int i = ty; i < 32; i += 8)
        g_acts[(size_t)(n0 + i) * BATCH + (b0 + tx)] = tile[tx][i];
}

// ---- gather: one block per target node, 128 threads, float4 over batch ----
// Each k-iteration: warp reads one contiguous 512B chunk of a 2KB source row.
__global__ void gather_kernel(const float* __restrict__ weight,
                              const int*   __restrict__ esrc,
                              const float* __restrict__ bias,
                              int s_node, int ebase) {
    __shared__ float sw[FAN_IN];
    __shared__ int   ss[FAN_IN];
    const int t    = threadIdx.x;
    const int base = ebase + blockIdx.x * FAN_IN;
    sw[t] = weight[base + t];
    ss[t] = esrc[base + t];
    __syncthreads();

    const int b0 = t * 4;
    const float* __restrict__ acts = g_acts;
    float4 acc = make_float4(0.f, 0.f, 0.f, 0.f);
    #pragma unroll 16
    for (int k = 0; k < FAN_IN; k++) {
        const float  w = sw[k];
        const float4 a = *reinterpret_cast<const float4*>(
            acts + (size_t)ss[k] * BATCH + b0);
        acc.x += w * a.x;
        acc.y += w * a.y;
        acc.z += w * a.z;
        acc.w += w * a.w;
    }
    const int   node = s_node + blockIdx.x;
    const float bb   = bias[node - INPUT_DIM];
    acc.x += bb; acc.y += bb; acc.z += bb; acc.w += bb;
    *reinterpret_cast<float4*>(&g_acts[(size_t)node * BATCH + b0]) = acc;
}

// ---- per-batch-column mean / rstd over the layer's nodes ------------------
// 16 blocks x 256 threads; each block owns 32 consecutive batch columns.
__global__ void reduce_kernel(int s_node, int dim) {
    const int tx = threadIdx.x & 31;   // batch column within block
    const int ty = threadIdx.x >> 5;   // node stride group (0..7)
    const int b  = blockIdx.x * 32 + tx;

    float sum = 0.f, sq = 0.f;
    for (int n = ty; n < dim; n += 8) {
        const float v = g_acts[(size_t)(s_node + n) * BATCH + b];
        sum += v;
        sq  += v * v;
    }
    __shared__ float ssum[8][32];
    __shared__ float ssq[8][32];
    ssum[ty][tx] = sum;
    ssq[ty][tx]  = sq;
    __syncthreads();
    if (ty == 0) {
        float tsum = 0.f, tsq = 0.f;
        #pragma unroll
        for (int j = 0; j < 8; j++) { tsum += ssum[j][tx]; tsq += ssq[j][tx]; }
        const float inv_dim = 1.0f / (float)dim;
        const float mean = tsum * inv_dim;
        const float var  = tsq * inv_dim - mean * mean;  // biased, as torch LN
        g_mean[b] = mean;
        g_rstd[b] = rsqrtf(var + LN_EPS);
    }
}

// ---- apply LayerNorm affine + ReLU in place -------------------------------
__global__ void norm_kernel(const float* __restrict__ gamma,
                            const float* __restrict__ beta,
                            int s_node) {
    const int node = s_node + blockIdx.x;
    const int b0   = threadIdx.x * 4;
    float4 v = *reinterpret_cast<float4*>(&g_acts[(size_t)node * BATCH + b0]);
    const float4 m = *reinterpret_cast<const float4*>(&g_mean[b0]);
    const float4 r = *reinterpret_cast<const float4*>(&g_rstd[b0]);
    const float g  = gamma[node - INPUT_DIM];
    const float be = beta[node - INPUT_DIM];
    v.x = fmaxf(g * (v.x - m.x) * r.x + be, 0.f);
    v.y = fmaxf(g * (v.y - m.y) * r.y + be, 0.f);
    v.z = fmaxf(g * (v.z - m.z) * r.z + be, 0.f);
    v.w = fmaxf(g * (v.w - m.w) * r.w + be, 0.f);
    *reinterpret_cast<float4*>(&g_acts[(size_t)node * BATCH + b0]) = v;
}

// ---- output layer (dim 2, no LN/ReLU): write d_out[b*2 + o] ---------------
__global__ void out_kernel(const float* __restrict__ weight,
                           const int*   __restrict__ esrc,
                           const float* __restrict__ bias,
                           float* __restrict__ out,
                           int ebase) {
    __shared__ float sw[FAN_IN];
    __shared__ int   ss[FAN_IN];
    const int t    = threadIdx.x;
    const int o    = blockIdx.x;             // 0 or 1
    const int base = ebase + o * FAN_IN;
    sw[t] = weight[base + t];
    ss[t] = esrc[base + t];
    __syncthreads();

    const int b0 = t * 4;
    float4 acc = make_float4(0.f, 0.f, 0.f, 0.f);
    #pragma unroll 16
    for (int k = 0; k < FAN_IN; k++) {
        const float  w = sw[k];
        const float4 a = *reinterpret_cast<const float4*>(
            &g_acts[(size_t)ss[k] * BATCH + b0]);
        acc.x += w * a.x;
        acc.y += w * a.y;
        acc.z += w * a.z;
        acc.w += w * a.w;
    }
    const float bb = bias[(7680 - INPUT_DIM) + o];
    out[(b0 + 0) * 2 + o] = acc.x + bb;
    out[(b0 + 1) * 2 + o] = acc.y + bb;
    out[(b0 + 2) * 2 + o] = acc.z + bb;
    out[(b0 + 3) * 2 + o] = acc.w + bb;
}

extern "C" void kernel_launch(void* const* d_in, const int* in_sizes, int n_in,
                              void* d_out, int out_size) {
    const float* x      = (const float*)d_in[0];
    const float* weight = (const float*)d_in[1];
    const float* bias   = (const float*)d_in[2];
    const float* gamma  = (const float*)d_in[3];
    const float* beta   = (const float*)d_in[4];
    const int*   esrc   = (const int*)  d_in[5];
    // d_in[6] = edge_tgt: implied by the contiguous per-target layout; unused.
    float* out = (float*)d_out;

    // x.T into activation scratch
    transpose_kernel<<<dim3(INPUT_DIM / 32, BATCH / 32), dim3(32, 8)>>>(x);

    // layer 1: nodes [4096, 6144), edges [0, 262144)
    gather_kernel<<<2048, 128>>>(weight, esrc, bias, 4096, 0);
    reduce_kernel<<<16, 256>>>(4096, 2048);
    norm_kernel<<<2048, 128>>>(gamma, beta, 4096);

    // layer 2: nodes [6144, 7168), edges [262144, 393216)
    gather_kernel<<<1024, 128>>>(weight, esrc, bias, 6144, 262144);
    reduce_kernel<<<16, 256>>>(6144, 1024);
    norm_kernel<<<1024, 128>>>(gamma, beta, 6144);

    // layer 3: nodes [7168, 7680), edges [393216, 458752)
    gather_kernel<<<512, 128>>>(weight, esrc, bias, 7168, 393216);
    reduce_kernel<<<16, 256>>>(7168, 512);
    norm_kernel<<<512, 128>>>(gamma, beta, 7168);

    // output layer: nodes [7680, 7682), edges [458752, 459008)
    out_kernel<<<2, 128>>>(weight, esrc, bias, out, 458752);
}

// round 9
// speedup vs baseline: 1.6135x; 1.6135x over previous
#include <cuda_runtime.h>
#include <cuda_fp16.h>

// ---------------------------------------------------------------------------
// SparseNetwork2: layered sparse MLP 4096 -> 2048 -> 1024 -> 512 -> 2
// FAN_IN = 128 edges per target, edges contiguous per target, so the
// reference's full-edge segment_sum collapses to a per-layer gather.
// R6 profile: gathers run at ~77% of the LTS cap (~9 TB/s on ~940 MB).
// R7: store activations as fp16 (fp32 accumulation) -> byte stream halves.
// ---------------------------------------------------------------------------

#define BATCH       512
#define INPUT_DIM   4096
#define TOTAL_NODES 7682
#define FAN_IN      128
#define LN_EPS      1e-5f

// 7.9 MB fp16 activation scratch (L2-resident)
__device__ __half g_acts[(size_t)TOTAL_NODES * BATCH];
__device__ float  g_mean[BATCH];
__device__ float  g_rstd[BATCH];

// ---- transpose x [B, INPUT_DIM] (fp32) -> g_acts[n*B + b] (fp16) ----------
__global__ void transpose_kernel(const float* __restrict__ x) {
    __shared__ float tile[32][33];
    const int n0 = blockIdx.x * 32;
    const int b0 = blockIdx.y * 32;
    const int tx = threadIdx.x, ty = threadIdx.y;
    #pragma unroll
    for (int i = ty; i < 32; i += 8)
        tile[i][tx] = x[(size_t)(b0 + i) * INPUT_DIM + (n0 + tx)];
    __syncthreads();
    #pragma unroll
    for (int i = ty; i < 32; i += 8)
        g_acts[(size_t)(n0 + i) * BATCH + (b0 + tx)] = __float2half_rn(tile[tx][i]);
}

// ---- gather: one block per target node, 128 threads, 4 cols/thread --------
// Per k-iteration a warp reads one contiguous 256B chunk of a 1KB fp16 row.
__global__ void gather_kernel(const float* __restrict__ weight,
                              const int*   __restrict__ esrc,
                              const float* __restrict__ bias,
                              int s_node, int ebase) {
    __shared__ float sw[FAN_IN];
    __shared__ int   ss[FAN_IN];
    const int t    = threadIdx.x;
    const int base = ebase + blockIdx.x * FAN_IN;
    sw[t] = weight[base + t];
    ss[t] = esrc[base + t];
    __syncthreads();

    const int b0 = t * 4;
    float4 acc = make_float4(0.f, 0.f, 0.f, 0.f);
    #pragma unroll 16
    for (int k = 0; k < FAN_IN; k++) {
        const float wk = sw[k];
        const uint2 u = *reinterpret_cast<const uint2*>(
            g_acts + (size_t)ss[k] * BATCH + b0);
        const float2 f0 = __half22float2(*reinterpret_cast<const __half2*>(&u.x));
        const float2 f1 = __half22float2(*reinterpret_cast<const __half2*>(&u.y));
        acc.x += wk * f0.x;
        acc.y += wk * f0.y;
        acc.z += wk * f1.x;
        acc.w += wk * f1.y;
    }
    const int   node = s_node + blockIdx.x;
    const float bb   = bias[node - INPUT_DIM];
    acc.x += bb; acc.y += bb; acc.z += bb; acc.w += bb;

    uint2 o;
    *reinterpret_cast<__half2*>(&o.x) = __floats2half2_rn(acc.x, acc.y);
    *reinterpret_cast<__half2*>(&o.y) = __floats2half2_rn(acc.z, acc.w);
    *reinterpret_cast<uint2*>(g_acts + (size_t)node * BATCH + b0) = o;
}

// ---- per-batch-column mean / rstd over the layer's nodes ------------------
// 64 blocks x 256 threads; each block owns 8 consecutive batch columns,
// 32 node-stride groups per column.
__global__ void reduce_kernel(int s_node, int dim) {
    const int tx = threadIdx.x & 7;    // batch column within block (0..7)
    const int ty = threadIdx.x >> 3;   // node stride group (0..31)
    const int b  = blockIdx.x * 8 + tx;

    float sum = 0.f, sq = 0.f;
    for (int n = ty; n < dim; n += 32) {
        const float v = __half2float(g_acts[(size_t)(s_node + n) * BATCH + b]);
        sum += v;
        sq  += v * v;
    }
    __shared__ float ssum[32][8];
    __shared__ float ssq[32][8];
    ssum[ty][tx] = sum;
    ssq[ty][tx]  = sq;
    __syncthreads();
    if (ty == 0) {
        float tsum = 0.f, tsq = 0.f;
        #pragma unroll
        for (int j = 0; j < 32; j++) { tsum += ssum[j][tx]; tsq += ssq[j][tx]; }
        const float inv_dim = 1.0f / (float)dim;
        const float mean = tsum * inv_dim;
        const float var  = tsq * inv_dim - mean * mean;  // biased, as torch LN
        g_mean[b] = mean;
        g_rstd[b] = rsqrtf(var + LN_EPS);
    }
}

// ---- apply LayerNorm affine + ReLU in place (fp16 storage) ----------------
__global__ void norm_kernel(const float* __restrict__ gamma,
                            const float* __restrict__ beta,
                            int s_node) {
    const int node = s_node + blockIdx.x;
    const int b0   = threadIdx.x * 4;
    uint2 u = *reinterpret_cast<uint2*>(g_acts + (size_t)node * BATCH + b0);
    float2 f0 = __half22float2(*reinterpret_cast<const __half2*>(&u.x));
    float2 f1 = __half22float2(*reinterpret_cast<const __half2*>(&u.y));
    const float4 m = *reinterpret_cast<const float4*>(&g_mean[b0]);
    const float4 r = *reinterpret_cast<const float4*>(&g_rstd[b0]);
    const float g  = gamma[node - INPUT_DIM];
    const float be = beta[node - INPUT_DIM];
    f0.x = fmaxf(g * (f0.x - m.x) * r.x + be, 0.f);
    f0.y = fmaxf(g * (f0.y - m.y) * r.y + be, 0.f);
    f1.x = fmaxf(g * (f1.x - m.z) * r.z + be, 0.f);
    f1.y = fmaxf(g * (f1.y - m.w) * r.w + be, 0.f);
    uint2 o;
    *reinterpret_cast<__half2*>(&o.x) = __floats2half2_rn(f0.x, f0.y);
    *reinterpret_cast<__half2*>(&o.y) = __floats2half2_rn(f1.x, f1.y);
    *reinterpret_cast<uint2*>(g_acts + (size_t)node * BATCH + b0) = o;
}

// ---- output layer (dim 2, no LN/ReLU): write d_out[b*2 + o] fp32 ----------
__global__ void out_kernel(const float* __restrict__ weight,
                           const int*   __restrict__ esrc,
                           const float* __restrict__ bias,
                           float* __restrict__ out,
                           int ebase) {
    __shared__ float sw[FAN_IN];
    __shared__ int   ss[FAN_IN];
    const int t    = threadIdx.x;
    const int o    = blockIdx.x;             // 0 or 1
    const int base = ebase + o * FAN_IN;
    sw[t] = weight[base + t];
    ss[t] = esrc[base + t];
    __syncthreads();

    const int b0 = t * 4;
    float4 acc = make_float4(0.f, 0.f, 0.f, 0.f);
    #pragma unroll 16
    for (int k = 0; k < FAN_IN; k++) {
        const float wk = sw[k];
        const uint2 u = *reinterpret_cast<const uint2*>(
            g_acts + (size_t)ss[k] * BATCH + b0);
        const float2 f0 = __half22float2(*reinterpret_cast<const __half2*>(&u.x));
        const float2 f1 = __half22float2(*reinterpret_cast<const __half2*>(&u.y));
        acc.x += wk * f0.x;
        acc.y += wk * f0.y;
        acc.z += wk * f1.x;
        acc.w += wk * f1.y;
    }
    const float bb = bias[(7680 - INPUT_DIM) + o];
    out[(b0 + 0) * 2 + o] = acc.x + bb;
    out[(b0 + 1) * 2 + o] = acc.y + bb;
    out[(b0 + 2) * 2 + o] = acc.z + bb;
    out[(b0 + 3) * 2 + o] = acc.w + bb;
}

extern "C" void kernel_launch(void* const* d_in, const int* in_sizes, int n_in,
                              void* d_out, int out_size) {
    const float* x      = (const float*)d_in[0];
    const float* weight = (const float*)d_in[1];
    const float* bias   = (const float*)d_in[2];
    const float* gamma  = (const float*)d_in[3];
    const float* beta   = (const float*)d_in[4];
    const int*   esrc   = (const int*)  d_in[5];
    // d_in[6] = edge_tgt: implied by the contiguous per-target layout; unused.
    float* out = (float*)d_out;

    // x.T into fp16 activation scratch
    transpose_kernel<<<dim3(INPUT_DIM / 32, BATCH / 32), dim3(32, 8)>>>(x);

    // layer 1: nodes [4096, 6144), edges [0, 262144)
    gather_kernel<<<2048, 128>>>(weight, esrc, bias, 4096, 0);
    reduce_kernel<<<64, 256>>>(4096, 2048);
    norm_kernel<<<2048, 128>>>(gamma, beta, 4096);

    // layer 2: nodes [6144, 7168), edges [262144, 393216)
    gather_kernel<<<1024, 128>>>(weight, esrc, bias, 6144, 262144);
    reduce_kernel<<<64, 256>>>(6144, 1024);
    norm_kernel<<<1024, 128>>>(gamma, beta, 6144);

    // layer 3: nodes [7168, 7680), edges [393216, 458752)
    gather_kernel<<<512, 128>>>(weight, esrc, bias, 7168, 393216);
    reduce_kernel<<<64, 256>>>(7168, 512);
    norm_kernel<<<512, 128>>>(gamma, beta, 7168);

    // output layer: nodes [7680, 7682), edges [458752, 459008)
    out_kernel<<<2, 128>>>(weight, esrc, bias, out, 458752);
}